// round 2
// baseline (speedup 1.0000x reference)
#include <cuda_runtime.h>

// ---------------------------------------------------------------------------
// GAT network, exploiting that the reference returns h[-1] (only node N-1).
// NOTE: edge_index is int32 on device (JAX x64 disabled downcasts jnp.int64).
// Dependency cone: TARGET <- S2 (in-neighbors of TARGET, ~17 nodes)
//                        <- U1 (in-neighbors of S2, ~290 nodes).
// Pipeline:
//   k0   clear flags/counters
//   k1   scan edges: collect edges with dst==TARGET, dedupe srcs into uniq2
//   k2   scan edges: collect edges with flagged dst; dedupe srcs into uniq1
//   k2b  add uniq2 nodes to uniq1 (self loops / dst features)
//   k3   h0 = x@W1 (+ a_s1/a_d1) for uniq1 nodes
//   k4   layer-1 GAT softmax-aggregate + bias + leaky(0.01) + BN1 -> h1
//   k5   ht2 = h1@W2 (+ a_s2/a_d2) for uniq2 nodes
//   k6   layer-2 GAT at TARGET + bias + leaky + BN2 + FC -> d_out[60]
// ---------------------------------------------------------------------------

#define NFLAG   131072     // >= N_NODES (100000)
#define MAX_S2  2048       // edges into TARGET (in-degree ~ Poisson(16))
#define MAX_U2  2048
#define MAX_E1  131072     // edges into uniq2 set (~290 expected)
#define MAX_U1  131072     // nodes needing h0 (~290 expected)
#define MAXDEG  2048       // per-dst in-degree cap inside k4

__device__ int   d_flag1[NFLAG], d_flag2[NFLAG];
__device__ int   d_idx1[NFLAG],  d_idx2[NFLAG];
__device__ int   d_s2src[MAX_S2];
__device__ int   d_uniq2[MAX_U2];
__device__ int   d_uniq1[MAX_U1];
__device__ int   d_e1src[MAX_E1], d_e1dst[MAX_E1];
__device__ int   d_cnt[4];           // 0:n_s2 1:n_u2 2:n_e1 3:n_u1
__device__ float d_h0[(size_t)MAX_U1 * 64];
__device__ float d_as1[MAX_U1 * 2],  d_ad1[MAX_U1 * 2];
__device__ float d_h1[MAX_U2 * 64];
__device__ float d_ht2[MAX_U2 * 128];
__device__ float d_as2[MAX_U2 * 2],  d_ad2[MAX_U2 * 2];

__device__ __forceinline__ float lrelu(float x, float s) {
    return x > 0.f ? x : s * x;
}

__device__ __forceinline__ void add_uniq2(int u) {
    if (atomicCAS(&d_flag2[u], 0, 1) == 0) {
        int p = atomicAdd(&d_cnt[1], 1);
        if (p < MAX_U2) { d_uniq2[p] = u; d_idx2[u] = p; }
    }
}
__device__ __forceinline__ void add_uniq1(int u) {
    if (atomicCAS(&d_flag1[u], 0, 1) == 0) {
        int p = atomicAdd(&d_cnt[3], 1);
        if (p < MAX_U1) { d_uniq1[p] = u; d_idx1[u] = p; }
    }
}

// block-wide reductions (nt = blockDim.x, power of 2)
__device__ __forceinline__ float bred_max(float v, float* sh, int nt) {
    int t = threadIdx.x;
    sh[t] = v; __syncthreads();
    for (int s = nt >> 1; s > 0; s >>= 1) {
        if (t < s) sh[t] = fmaxf(sh[t], sh[t + s]);
        __syncthreads();
    }
    float r = sh[0]; __syncthreads();
    return r;
}
__device__ __forceinline__ float bred_sum(float v, float* sh, int nt) {
    int t = threadIdx.x;
    sh[t] = v; __syncthreads();
    for (int s = nt >> 1; s > 0; s >>= 1) {
        if (t < s) sh[t] = sh[t] + sh[t + s];
        __syncthreads();
    }
    float r = sh[0]; __syncthreads();
    return r;
}

// ---- k0: clear -------------------------------------------------------------
__global__ void k0_clear() {
    int i = blockIdx.x * blockDim.x + threadIdx.x;
    int stride = gridDim.x * blockDim.x;
    for (int j = i; j < NFLAG; j += stride) { d_flag1[j] = 0; d_flag2[j] = 0; }
    if (i < 4) d_cnt[i] = 0;
}

// ---- k1: edges into TARGET -------------------------------------------------
__global__ void k1_frontier2(const int* __restrict__ ei, int E, int target) {
    int i = blockIdx.x * blockDim.x + threadIdx.x;
    int stride = gridDim.x * blockDim.x;
    if (i == 0) add_uniq2(target);   // self-loop node
    for (; i < E; i += stride) {
        int dst = ei[E + i];
        if (dst == target) {
            int src = ei[i];
            int p = atomicAdd(&d_cnt[0], 1);
            if (p < MAX_S2) d_s2src[p] = src;
            add_uniq2(src);
        }
    }
}

// ---- k2: edges into uniq2 set ---------------------------------------------
__global__ void k2_frontier1(const int* __restrict__ ei, int E) {
    int i = blockIdx.x * blockDim.x + threadIdx.x;
    int stride = gridDim.x * blockDim.x;
    for (; i < E; i += stride) {
        int dst = ei[E + i];
        if (d_flag2[dst]) {
            int src = ei[i];
            int p = atomicAdd(&d_cnt[2], 1);
            if (p < MAX_E1) { d_e1src[p] = src; d_e1dst[p] = dst; }
            add_uniq1(src);
        }
    }
}

__global__ void k2b_selfnodes() {
    int n = min(d_cnt[1], MAX_U2);
    for (int t = threadIdx.x; t < n; t += blockDim.x) add_uniq1(d_uniq2[t]);
}

// ---- k3: h0 = x@W1, a_s1, a_d1 for uniq1 nodes (64 threads/block) ---------
__global__ void k3_h0(const float* __restrict__ x, const float* __restrict__ W1,
                      const float* __restrict__ asrc1, const float* __restrict__ adst1) {
    __shared__ float xs[128];
    int nu = min(d_cnt[3], MAX_U1);
    int j = threadIdx.x;   // 0..63
    for (int ui = blockIdx.x; ui < nu; ui += gridDim.x) {
        int u = d_uniq1[ui];
        xs[j]      = x[(size_t)u * 128 + j];
        xs[j + 64] = x[(size_t)u * 128 + 64 + j];
        __syncthreads();
        float acc = 0.f;
        #pragma unroll
        for (int k = 0; k < 128; k++) acc = fmaf(xs[k], W1[k * 64 + j], acc);
        d_h0[(size_t)ui * 64 + j] = acc;
        // per-head dots: head = j>>5, a_src1 flat[64] matches h layout
        float vs = acc * asrc1[j];
        float vd = acc * adst1[j];
        #pragma unroll
        for (int o = 16; o > 0; o >>= 1) {
            vs += __shfl_xor_sync(0xffffffffu, vs, o);
            vd += __shfl_xor_sync(0xffffffffu, vd, o);
        }
        if ((j & 31) == 0) {
            int h = j >> 5;
            d_as1[ui * 2 + h] = vs;
            d_ad1[ui * 2 + h] = vd;
        }
        __syncthreads();
    }
}

// ---- k4: layer-1 GAT aggregate at uniq2 nodes (64 threads/block) ----------
__global__ void k4_layer1(const float* __restrict__ b1,
                          const float* __restrict__ g1, const float* __restrict__ be1,
                          const float* __restrict__ mn1, const float* __restrict__ vr1) {
    __shared__ int   s_si[MAXDEG];
    __shared__ float s_a0[MAXDEG], s_a1[MAXDEG];
    __shared__ float red[64];
    __shared__ int   scnt;
    int nv = min(d_cnt[1], MAX_U2);
    int ne = min(d_cnt[2], MAX_E1);
    int tid = threadIdx.x;   // 0..63
    for (int vi = blockIdx.x; vi < nv; vi += gridDim.x) {
        int vnode = d_uniq2[vi];
        int vIdx  = d_idx1[vnode];
        float ad0 = d_ad1[vIdx * 2 + 0];
        float ad1 = d_ad1[vIdx * 2 + 1];
        if (tid == 0) scnt = 0;
        __syncthreads();
        // gather matched edges (+ one self loop at virtual index ne)
        for (int i = tid; i <= ne; i += 64) {
            int s;
            if (i == ne) s = vnode;
            else { if (d_e1dst[i] != vnode) continue; s = d_e1src[i]; }
            int p = atomicAdd(&scnt, 1);
            if (p < MAXDEG) s_si[p] = d_idx1[s];
        }
        __syncthreads();
        int cnt = min(scnt, MAXDEG);
        // attention logits + max
        float lm0 = -1e30f, lm1 = -1e30f;
        for (int k = tid; k < cnt; k += 64) {
            int si = s_si[k];
            float e0 = lrelu(d_as1[si * 2 + 0] + ad0, 0.2f);
            float e1 = lrelu(d_as1[si * 2 + 1] + ad1, 0.2f);
            s_a0[k] = e0; s_a1[k] = e1;
            lm0 = fmaxf(lm0, e0); lm1 = fmaxf(lm1, e1);
        }
        float m0 = bred_max(lm0, red, 64);
        float m1 = bred_max(lm1, red, 64);
        float ls0 = 0.f, ls1 = 0.f;
        for (int k = tid; k < cnt; k += 64) {
            float a0 = expf(s_a0[k] - m0);
            float a1 = expf(s_a1[k] - m1);
            s_a0[k] = a0; s_a1[k] = a1;
            ls0 += a0; ls1 += a1;
        }
        float sum0 = bred_sum(ls0, red, 64);
        float sum1 = bred_sum(ls1, red, 64);
        int j = tid;
        float inv = (j >= 32) ? 1.f / (sum1 + 1e-16f) : 1.f / (sum0 + 1e-16f);
        const float* sa = (j >= 32) ? s_a1 : s_a0;
        float acc = 0.f;
        for (int k = 0; k < cnt; k++)
            acc = fmaf(sa[k], d_h0[(size_t)s_si[k] * 64 + j], acc);
        acc *= inv;
        float o = acc + b1[j];
        o = lrelu(o, 0.01f);
        o = (o - mn1[j]) * rsqrtf(vr1[j] + 1e-5f) * g1[j] + be1[j];
        d_h1[vi * 64 + j] = o;
        __syncthreads();
    }
}

// ---- k5: ht2 = h1@W2, a_s2, a_d2 for uniq2 nodes (128 threads/block) ------
__global__ void k5_ht2(const float* __restrict__ W2,
                       const float* __restrict__ asrc2, const float* __restrict__ adst2) {
    __shared__ float hs[64];
    __shared__ float ss[4], sd[4];
    int nv = min(d_cnt[1], MAX_U2);
    int j = threadIdx.x;   // 0..127
    for (int vi = blockIdx.x; vi < nv; vi += gridDim.x) {
        if (j < 64) hs[j] = d_h1[vi * 64 + j];
        __syncthreads();
        float acc = 0.f;
        #pragma unroll
        for (int k = 0; k < 64; k++) acc = fmaf(hs[k], W2[k * 128 + j], acc);
        d_ht2[(size_t)vi * 128 + j] = acc;
        float vs = acc * asrc2[j];
        float vd = acc * adst2[j];
        #pragma unroll
        for (int o = 16; o > 0; o >>= 1) {
            vs += __shfl_xor_sync(0xffffffffu, vs, o);
            vd += __shfl_xor_sync(0xffffffffu, vd, o);
        }
        int w = j >> 5;
        if ((j & 31) == 0) { ss[w] = vs; sd[w] = vd; }
        __syncthreads();
        if (j == 0) {
            d_as2[vi * 2 + 0] = ss[0] + ss[1];
            d_as2[vi * 2 + 1] = ss[2] + ss[3];
            d_ad2[vi * 2 + 0] = sd[0] + sd[1];
            d_ad2[vi * 2 + 1] = sd[2] + sd[3];
        }
        __syncthreads();
    }
}

// ---- k6: layer-2 GAT at TARGET + BN + FC (1 block, 128 threads) -----------
__global__ void k6_final(const float* __restrict__ b2,
                         const float* __restrict__ g2, const float* __restrict__ be2,
                         const float* __restrict__ mn2, const float* __restrict__ vr2,
                         const float* __restrict__ fcW, const float* __restrict__ fcb,
                         float* __restrict__ out, int target) {
    __shared__ int   s_si[MAX_S2 + 1];
    __shared__ float s_a0[MAX_S2 + 1], s_a1[MAX_S2 + 1];
    __shared__ float red[128];
    __shared__ float hfin[128];
    int tid = threadIdx.x;   // 0..127
    int u_t = d_idx2[target];
    float ad0 = d_ad2[u_t * 2 + 0];
    float ad1 = d_ad2[u_t * 2 + 1];
    int n = min(d_cnt[0], MAX_S2);
    int cnt = n + 1;                      // + self loop
    float lm0 = -1e30f, lm1 = -1e30f;
    for (int k = tid; k < cnt; k += 128) {
        int src = (k == n) ? target : d_s2src[k];
        int si = d_idx2[src];
        s_si[k] = si;
        float e0 = lrelu(d_as2[si * 2 + 0] + ad0, 0.2f);
        float e1 = lrelu(d_as2[si * 2 + 1] + ad1, 0.2f);
        s_a0[k] = e0; s_a1[k] = e1;
        lm0 = fmaxf(lm0, e0); lm1 = fmaxf(lm1, e1);
    }
    float m0 = bred_max(lm0, red, 128);
    float m1 = bred_max(lm1, red, 128);
    float ls0 = 0.f, ls1 = 0.f;
    for (int k = tid; k < cnt; k += 128) {
        float a0 = expf(s_a0[k] - m0);
        float a1 = expf(s_a1[k] - m1);
        s_a0[k] = a0; s_a1[k] = a1;
        ls0 += a0; ls1 += a1;
    }
    float sum0 = bred_sum(ls0, red, 128);
    float sum1 = bred_sum(ls1, red, 128);
    int j = tid;
    float inv = (j >= 64) ? 1.f / (sum1 + 1e-16f) : 1.f / (sum0 + 1e-16f);
    const float* sa = (j >= 64) ? s_a1 : s_a0;
    float acc = 0.f;
    for (int k = 0; k < cnt; k++)
        acc = fmaf(sa[k], d_ht2[(size_t)s_si[k] * 128 + j], acc);
    acc *= inv;
    float o = acc + b2[j];
    o = lrelu(o, 0.01f);
    o = (o - mn2[j]) * rsqrtf(vr2[j] + 1e-5f) * g2[j] + be2[j];
    hfin[j] = o;
    __syncthreads();
    if (j < 60) {
        float r = fcb[j];
        #pragma unroll 4
        for (int q = 0; q < 128; q++) r = fmaf(hfin[q], fcW[q * 60 + j], r);
        out[j] = r;
    }
}

// ---------------------------------------------------------------------------
extern "C" void kernel_launch(void* const* d_in, const int* in_sizes, int n_in,
                              void* d_out, int out_size) {
    const float* x      = (const float*)d_in[0];
    const int*   ei     = (const int*)d_in[1];     // int32 (JAX x64 disabled)
    const float* W1     = (const float*)d_in[2];
    const float* asrc1  = (const float*)d_in[3];
    const float* adst1  = (const float*)d_in[4];
    const float* b1     = (const float*)d_in[5];
    const float* g1     = (const float*)d_in[6];
    const float* be1    = (const float*)d_in[7];
    const float* mn1    = (const float*)d_in[8];
    const float* vr1    = (const float*)d_in[9];
    const float* W2     = (const float*)d_in[10];
    const float* asrc2  = (const float*)d_in[11];
    const float* adst2  = (const float*)d_in[12];
    const float* b2     = (const float*)d_in[13];
    const float* g2     = (const float*)d_in[14];
    const float* be2    = (const float*)d_in[15];
    const float* mn2    = (const float*)d_in[16];
    const float* vr2    = (const float*)d_in[17];
    const float* fcW    = (const float*)d_in[18];
    const float* fcb    = (const float*)d_in[19];
    float*       out    = (float*)d_out;

    int N = in_sizes[0] / 128;
    int E = in_sizes[1] / 2;
    int target = N - 1;

    k0_clear     <<<256, 256>>>();
    k1_frontier2 <<<2048, 256>>>(ei, E, target);
    k2_frontier1 <<<2048, 256>>>(ei, E);
    k2b_selfnodes<<<1, 256>>>();
    k3_h0        <<<512, 64>>>(x, W1, asrc1, adst1);
    k4_layer1    <<<256, 64>>>(b1, g1, be1, mn1, vr1);
    k5_ht2       <<<128, 128>>>(W2, asrc2, adst2);
    k6_final     <<<1, 128>>>(b2, g2, be2, mn2, vr2, fcW, fcb, out, target);
}

// round 4
// speedup vs baseline: 1.1357x; 1.1357x over previous
#include <cuda_runtime.h>

// ---------------------------------------------------------------------------
// GAT network returning only h[N-1]: dependency-cone pruning, single
// persistent kernel with software grid barriers. NB=148 (1 block/SM) so
// co-residency of all blocks is guaranteed.
//
// Phases (grid barriers between):
//  P1: scan dst[] for edges into TARGET -> s2src list, uniq2 set (+uniq1)
//  P2: scan dst[] with shared-mem bitmap of uniq2 -> e1 edge list, uniq1 set
//  P3: h0 = x@W1 (+ head dots a_s1/a_d1) for all uniq1 nodes
//  P4: per uniq2 node: layer-1 GAT softmax-agg + bias + leaky + BN1 -> h1,
//      then immediately ht2 = h1@W2 (+ a_s2/a_d2)
//  P5: (block 0) layer-2 GAT at TARGET + bias + leaky + BN2 + FC -> out[60];
//      then clear touched flags/counters so next graph replay starts clean.
// ---------------------------------------------------------------------------

#define NB       148        // 1 block per SM -> guaranteed co-resident
#define NT       256
#define MAX_S2   512        // edges into TARGET (Poisson(16))
#define MAX_U2   512
#define MAX_U1   8192       // cone nodes (~300 expected)
#define MAX_E1   16384      // cone edges (~290 expected)
#define MAXD     512        // per-node in-degree cap (incl. self loop)
#define NFLAG    131072
#define BMWORDS  4096       // 131072 bits >= N_NODES

__device__ int   d_flag1[NFLAG], d_flag2[NFLAG];
__device__ int   d_idx1[NFLAG],  d_idx2[NFLAG];
__device__ int   d_s2src[MAX_S2];
__device__ int   d_uniq2[MAX_U2];
__device__ int   d_uniq1[MAX_U1];
__device__ int   d_e1src[MAX_E1], d_e1dst[MAX_E1];
__device__ int   d_cnt[4];                 // 0:n_s2 1:n_u2 2:n_e1 3:n_u1
__device__ float d_h0[MAX_U1 * 64];
__device__ float d_as1[MAX_U1 * 2], d_ad1[MAX_U1 * 2];
__device__ float d_ht2[MAX_U2 * 128];
__device__ float d_as2[MAX_U2 * 2], d_ad2[MAX_U2 * 2];
__device__ volatile int d_bar_gen;
__device__ int   d_bar_cnt;

__device__ __forceinline__ float lrelu(float x, float s) {
    return x > 0.f ? x : s * x;
}

__device__ __forceinline__ void add_uniq2(int u) {
    if (atomicCAS(&d_flag2[u], 0, 1) == 0) {
        int p = atomicAdd(&d_cnt[1], 1);
        if (p < MAX_U2) { d_uniq2[p] = u; d_idx2[u] = p; }
    }
}
__device__ __forceinline__ void add_uniq1(int u) {
    if (atomicCAS(&d_flag1[u], 0, 1) == 0) {
        int p = atomicAdd(&d_cnt[3], 1);
        if (p < MAX_U1) { d_uniq1[p] = u; d_idx1[u] = p; }
    }
}

// grid-wide barrier: all NB blocks must call
__device__ __forceinline__ void gsync() {
    __syncthreads();
    if (threadIdx.x == 0) {
        __threadfence();
        int g = d_bar_gen;
        if (atomicAdd(&d_bar_cnt, 1) == NB - 1) {
            d_bar_cnt = 0;
            __threadfence();
            d_bar_gen = g + 1;
        } else {
            while (d_bar_gen == g) { __nanosleep(32); }
        }
        __threadfence();
    }
    __syncthreads();
}

__global__ void __launch_bounds__(NT, 1)
gat_fused(const float* __restrict__ x,   const int* __restrict__ ei,
          const float* __restrict__ W1,  const float* __restrict__ asrc1,
          const float* __restrict__ adst1, const float* __restrict__ b1,
          const float* __restrict__ g1,  const float* __restrict__ be1,
          const float* __restrict__ mn1, const float* __restrict__ vr1,
          const float* __restrict__ W2,  const float* __restrict__ asrc2,
          const float* __restrict__ adst2, const float* __restrict__ b2,
          const float* __restrict__ g2,  const float* __restrict__ be2,
          const float* __restrict__ mn2, const float* __restrict__ vr2,
          const float* __restrict__ fcW, const float* __restrict__ fcb,
          float* __restrict__ out, int E, int target)
{
    __shared__ unsigned s_bm[BMWORDS];             // 16 KB bitmap (P2)
    __shared__ int   s_si[MAXD + 8];
    __shared__ float s_a0[MAXD + 8], s_a1[MAXD + 8];
    __shared__ float xs[128], part[NT], red[NT], hs[128];
    __shared__ float ss[4], sd[4];
    __shared__ int   s_scnt;

    const int tid  = threadIdx.x;
    const int gtid = blockIdx.x * NT + tid;
    const int gstr = NB * NT;
    const int* dstp = ei + E;
    const int n4 = E >> 2;

    // ---------------- P1: edges into TARGET --------------------------------
    if (gtid == 0) { add_uniq2(target); add_uniq1(target); }
    {
        const int4* d4 = (const int4*)dstp;
        for (int i = gtid; i < n4; i += gstr) {
            int4 d = d4[i];
            if (d.x == target) { int s = ei[4*i+0]; int p = atomicAdd(&d_cnt[0],1); if (p<MAX_S2) d_s2src[p]=s; add_uniq2(s); add_uniq1(s); }
            if (d.y == target) { int s = ei[4*i+1]; int p = atomicAdd(&d_cnt[0],1); if (p<MAX_S2) d_s2src[p]=s; add_uniq2(s); add_uniq1(s); }
            if (d.z == target) { int s = ei[4*i+2]; int p = atomicAdd(&d_cnt[0],1); if (p<MAX_S2) d_s2src[p]=s; add_uniq2(s); add_uniq1(s); }
            if (d.w == target) { int s = ei[4*i+3]; int p = atomicAdd(&d_cnt[0],1); if (p<MAX_S2) d_s2src[p]=s; add_uniq2(s); add_uniq1(s); }
        }
        for (int e = (n4 << 2) + gtid; e < E; e += gstr) {
            if (dstp[e] == target) { int s = ei[e]; int p = atomicAdd(&d_cnt[0],1); if (p<MAX_S2) d_s2src[p]=s; add_uniq2(s); add_uniq1(s); }
        }
    }
    gsync();

    // ---------------- P2: edges into uniq2 (shared bitmap) ------------------
    {
        for (int w = tid; w < BMWORDS; w += NT) s_bm[w] = 0u;
        __syncthreads();
        int n2 = min(d_cnt[1], MAX_U2);
        for (int t = tid; t < n2; t += NT) {
            int u = d_uniq2[t];
            atomicOr(&s_bm[u >> 5], 1u << (u & 31));
        }
        __syncthreads();
        const int4* d4 = (const int4*)dstp;
        for (int i = gtid; i < n4; i += gstr) {
            int4 d = d4[i];
            unsigned h0b = (s_bm[d.x >> 5] >> (d.x & 31)) & 1u;
            unsigned h1b = (s_bm[d.y >> 5] >> (d.y & 31)) & 1u;
            unsigned h2b = (s_bm[d.z >> 5] >> (d.z & 31)) & 1u;
            unsigned h3b = (s_bm[d.w >> 5] >> (d.w & 31)) & 1u;
            if (h0b) { int s = ei[4*i+0]; int p = atomicAdd(&d_cnt[2],1); if (p<MAX_E1){d_e1src[p]=s; d_e1dst[p]=d.x;} add_uniq1(s); }
            if (h1b) { int s = ei[4*i+1]; int p = atomicAdd(&d_cnt[2],1); if (p<MAX_E1){d_e1src[p]=s; d_e1dst[p]=d.y;} add_uniq1(s); }
            if (h2b) { int s = ei[4*i+2]; int p = atomicAdd(&d_cnt[2],1); if (p<MAX_E1){d_e1src[p]=s; d_e1dst[p]=d.z;} add_uniq1(s); }
            if (h3b) { int s = ei[4*i+3]; int p = atomicAdd(&d_cnt[2],1); if (p<MAX_E1){d_e1src[p]=s; d_e1dst[p]=d.w;} add_uniq1(s); }
        }
        for (int e = (n4 << 2) + gtid; e < E; e += gstr) {
            int d = dstp[e];
            if ((s_bm[d >> 5] >> (d & 31)) & 1u) {
                int s = ei[e]; int p = atomicAdd(&d_cnt[2],1);
                if (p < MAX_E1) { d_e1src[p]=s; d_e1dst[p]=d; }
                add_uniq1(s);
            }
        }
    }
    gsync();

    // ---------------- P3: h0 = x@W1 for uniq1 nodes -------------------------
    {
        int nu = min(d_cnt[3], MAX_U1);
        int j  = tid & 63;
        int kq = tid >> 6;          // 0..3
        for (int ui = blockIdx.x; ui < nu; ui += NB) {
            int u = d_uniq1[ui];
            if (tid < 128) xs[tid] = x[(size_t)u * 128 + tid];
            __syncthreads();
            float acc = 0.f;
            #pragma unroll
            for (int k = 0; k < 32; k++)
                acc = fmaf(xs[kq * 32 + k], W1[(kq * 32 + k) * 64 + j], acc);
            part[tid] = acc;
            __syncthreads();
            if (tid < 64) {
                float h = part[j] + part[j + 64] + part[j + 128] + part[j + 192];
                d_h0[ui * 64 + j] = h;
                float vs = h * asrc1[j];
                float vd = h * adst1[j];
                #pragma unroll
                for (int o = 16; o > 0; o >>= 1) {
                    vs += __shfl_xor_sync(0xffffffffu, vs, o);
                    vd += __shfl_xor_sync(0xffffffffu, vd, o);
                }
                if ((j & 31) == 0) {
                    int hh = j >> 5;
                    d_as1[ui * 2 + hh] = vs;
                    d_ad1[ui * 2 + hh] = vd;
                }
            }
            __syncthreads();
        }
    }
    gsync();

    // ---------------- P4: layer-1 GAT + projection per uniq2 node -----------
    {
        int nv = min(d_cnt[1], MAX_U2);
        int ne = min(d_cnt[2], MAX_E1);
        for (int vi = blockIdx.x; vi < nv; vi += NB) {
            int vnode = d_uniq2[vi];
            int vIdx  = d_idx1[vnode];
            float ad0 = d_ad1[vIdx * 2 + 0];
            float ad1 = d_ad1[vIdx * 2 + 1];
            if (tid == 0) { s_scnt = 1; s_si[0] = vIdx; }   // self loop
            __syncthreads();
            for (int i = tid; i < ne; i += NT) {
                if (d_e1dst[i] == vnode) {
                    int p = atomicAdd(&s_scnt, 1);
                    if (p < MAXD) s_si[p] = d_idx1[d_e1src[i]];
                }
            }
            __syncthreads();
            int cnt = min(s_scnt, MAXD);
            float lm0 = -1e30f, lm1 = -1e30f;
            for (int k = tid; k < cnt; k += NT) {
                int si = s_si[k];
                float e0 = lrelu(d_as1[si * 2 + 0] + ad0, 0.2f);
                float e1 = lrelu(d_as1[si * 2 + 1] + ad1, 0.2f);
                s_a0[k] = e0; s_a1[k] = e1;
                lm0 = fmaxf(lm0, e0); lm1 = fmaxf(lm1, e1);
            }
            // block max
            red[tid] = lm0; __syncthreads();
            for (int s = NT >> 1; s > 0; s >>= 1) { if (tid < s) red[tid] = fmaxf(red[tid], red[tid + s]); __syncthreads(); }
            float m0 = red[0]; __syncthreads();
            red[tid] = lm1; __syncthreads();
            for (int s = NT >> 1; s > 0; s >>= 1) { if (tid < s) red[tid] = fmaxf(red[tid], red[tid + s]); __syncthreads(); }
            float m1 = red[0]; __syncthreads();
            float ls0 = 0.f, ls1 = 0.f;
            for (int k = tid; k < cnt; k += NT) {
                float a0 = expf(s_a0[k] - m0);
                float a1 = expf(s_a1[k] - m1);
                s_a0[k] = a0; s_a1[k] = a1;
                ls0 += a0; ls1 += a1;
            }
            red[tid] = ls0; __syncthreads();
            for (int s = NT >> 1; s > 0; s >>= 1) { if (tid < s) red[tid] += red[tid + s]; __syncthreads(); }
            float sum0 = red[0]; __syncthreads();
            red[tid] = ls1; __syncthreads();
            for (int s = NT >> 1; s > 0; s >>= 1) { if (tid < s) red[tid] += red[tid + s]; __syncthreads(); }
            float sum1 = red[0]; __syncthreads();
            if (tid < 64) {
                int j = tid;
                const float* sa = (j >= 32) ? s_a1 : s_a0;
                float inv = (j >= 32) ? 1.f / (sum1 + 1e-16f) : 1.f / (sum0 + 1e-16f);
                float acc = 0.f;
                for (int k = 0; k < cnt; k++)
                    acc = fmaf(sa[k], d_h0[s_si[k] * 64 + j], acc);
                acc *= inv;
                float o = acc + b1[j];
                o = lrelu(o, 0.01f);
                o = (o - mn1[j]) * rsqrtf(vr1[j] + 1e-5f) * g1[j] + be1[j];
                hs[j] = o;
            }
            __syncthreads();
            if (tid < 128) {
                int j = tid;
                float acc = 0.f;
                #pragma unroll
                for (int k = 0; k < 64; k++) acc = fmaf(hs[k], W2[k * 128 + j], acc);
                d_ht2[vi * 128 + j] = acc;
                float vs = acc * asrc2[j];
                float vd = acc * adst2[j];
                #pragma unroll
                for (int o = 16; o > 0; o >>= 1) {
                    vs += __shfl_xor_sync(0xffffffffu, vs, o);
                    vd += __shfl_xor_sync(0xffffffffu, vd, o);
                }
                int w = j >> 5;
                if ((j & 31) == 0) { ss[w] = vs; sd[w] = vd; }
            }
            __syncthreads();
            if (tid == 0) {
                d_as2[vi * 2 + 0] = ss[0] + ss[1];
                d_as2[vi * 2 + 1] = ss[2] + ss[3];
                d_ad2[vi * 2 + 0] = sd[0] + sd[1];
                d_ad2[vi * 2 + 1] = sd[2] + sd[3];
            }
            __syncthreads();
        }
    }
    gsync();

    // ---------------- P5: layer-2 at TARGET + FC + cleanup (block 0) --------
    if (blockIdx.x != 0) return;
    {
        int u_t = d_idx2[target];
        float ad0 = d_ad2[u_t * 2 + 0];
        float ad1 = d_ad2[u_t * 2 + 1];
        int n = min(d_cnt[0], MAX_S2);
        int cnt = n + 1;                       // + self loop
        float lm0 = -1e30f, lm1 = -1e30f;
        for (int k = tid; k < cnt; k += NT) {
            int src = (k == n) ? target : d_s2src[k];
            int si = d_idx2[src];
            s_si[k] = si;
            float e0 = lrelu(d_as2[si * 2 + 0] + ad0, 0.2f);
            float e1 = lrelu(d_as2[si * 2 + 1] + ad1, 0.2f);
            s_a0[k] = e0; s_a1[k] = e1;
            lm0 = fmaxf(lm0, e0); lm1 = fmaxf(lm1, e1);
        }
        red[tid] = lm0; __syncthreads();
        for (int s = NT >> 1; s > 0; s >>= 1) { if (tid < s) red[tid] = fmaxf(red[tid], red[tid + s]); __syncthreads(); }
        float m0 = red[0]; __syncthreads();
        red[tid] = lm1; __syncthreads();
        for (int s = NT >> 1; s > 0; s >>= 1) { if (tid < s) red[tid] = fmaxf(red[tid], red[tid + s]); __syncthreads(); }
        float m1 = red[0]; __syncthreads();
        float ls0 = 0.f, ls1 = 0.f;
        for (int k = tid; k < cnt; k += NT) {
            float a0 = expf(s_a0[k] - m0);
            float a1 = expf(s_a1[k] - m1);
            s_a0[k] = a0; s_a1[k] = a1;
            ls0 += a0; ls1 += a1;
        }
        red[tid] = ls0; __syncthreads();
        for (int s = NT >> 1; s > 0; s >>= 1) { if (tid < s) red[tid] += red[tid + s]; __syncthreads(); }
        float sum0 = red[0]; __syncthreads();
        red[tid] = ls1; __syncthreads();
        for (int s = NT >> 1; s > 0; s >>= 1) { if (tid < s) red[tid] += red[tid + s]; __syncthreads(); }
        float sum1 = red[0]; __syncthreads();
        if (tid < 128) {
            int j = tid;
            const float* sa = (j >= 64) ? s_a1 : s_a0;
            float inv = (j >= 64) ? 1.f / (sum1 + 1e-16f) : 1.f / (sum0 + 1e-16f);
            float acc = 0.f;
            for (int k = 0; k < cnt; k++)
                acc = fmaf(sa[k], d_ht2[s_si[k] * 128 + j], acc);
            acc *= inv;
            float o = acc + b2[j];
            o = lrelu(o, 0.01f);
            o = (o - mn2[j]) * rsqrtf(vr2[j] + 1e-5f) * g2[j] + be2[j];
            hs[j] = o;
        }
        __syncthreads();
        if (tid < 60) {
            float r = fcb[tid];
            #pragma unroll 4
            for (int q = 0; q < 128; q++) r = fmaf(hs[q], fcW[q * 60 + tid], r);
            out[tid] = r;
        }
        // cleanup for next graph replay
        __syncthreads();
        int n1c = min(d_cnt[3], MAX_U1);
        for (int i = tid; i < n1c; i += NT) d_flag1[d_uniq1[i]] = 0;
        int n2c = min(d_cnt[1], MAX_U2);
        for (int i = tid; i < n2c; i += NT) d_flag2[d_uniq2[i]] = 0;
        __syncthreads();
        if (tid < 4) d_cnt[tid] = 0;
    }
}

// ---------------------------------------------------------------------------
extern "C" void kernel_launch(void* const* d_in, const int* in_sizes, int n_in,
                              void* d_out, int out_size) {
    const float* x      = (const float*)d_in[0];
    const int*   ei     = (const int*)d_in[1];     // int32 (JAX x64 disabled)
    const float* W1     = (const float*)d_in[2];
    const float* asrc1  = (const float*)d_in[3];
    const float* adst1  = (const float*)d_in[4];
    const float* b1     = (const float*)d_in[5];
    const float* g1     = (const float*)d_in[6];
    const float* be1    = (const float*)d_in[7];
    const float* mn1    = (const float*)d_in[8];
    const float* vr1    = (const float*)d_in[9];
    const float* W2     = (const float*)d_in[10];
    const float* asrc2  = (const float*)d_in[11];
    const float* adst2  = (const float*)d_in[12];
    const float* b2     = (const float*)d_in[13];
    const float* g2     = (const float*)d_in[14];
    const float* be2    = (const float*)d_in[15];
    const float* mn2    = (const float*)d_in[16];
    const float* vr2    = (const float*)d_in[17];
    const float* fcW    = (const float*)d_in[18];
    const float* fcb    = (const float*)d_in[19];
    float*       out    = (float*)d_out;

    int N = in_sizes[0] / 128;
    int E = in_sizes[1] / 2;
    int target = N - 1;

    gat_fused<<<NB, NT>>>(x, ei, W1, asrc1, adst1, b1, g1, be1, mn1, vr1,
                          W2, asrc2, adst2, b2, g2, be2, mn2, vr2, fcW, fcb,
                          out, E, target);
}

// round 6
// speedup vs baseline: 1.1617x; 1.0229x over previous
#include <cuda_runtime.h>

// ---------------------------------------------------------------------------
// GAT network returning only h[N-1]: dependency-cone pruning, single
// persistent kernel with software grid barriers. NB=148 (1 block/SM),
// NT=512 (16 warps/SM). Scans use 4-way unrolled independent loads (MLP=4).
//
// Phases (grid barriers between):
//  P1: scan dst[] for edges into TARGET -> s2src list, uniq2 set (+uniq1)
//  P2: scan dst[] with shared-mem bitmap of uniq2 -> e1 edge list, uniq1 set
//  P3: h0 = x@W1 (+ head dots a_s1/a_d1) for all uniq1 nodes
//  P4: per uniq2 node: layer-1 GAT softmax-agg + bias + leaky + BN1 -> h1,
//      then immediately ht2 = h1@W2 (+ a_s2/a_d2)
//  P5: (block 0) layer-2 GAT at TARGET + bias + leaky + BN2 + FC -> out[60];
//      then clear touched flags/counters so next graph replay starts clean.
// ---------------------------------------------------------------------------

#define NB       148        // 1 block per SM -> guaranteed co-resident
#define NT       512
#define SCAN_U   4          // unroll factor for edge scans (MLP)
#define MAX_S2   512        // edges into TARGET (Poisson(16))
#define MAX_U2   512
#define MAX_U1   8192       // cone nodes (~300 expected)
#define MAX_E1   16384      // cone edges (~290 expected)
#define MAXD     512        // per-node in-degree cap (incl. self loop)
#define NFLAG    131072
#define BMWORDS  4096       // 131072 bits >= N_NODES

__device__ int   d_flag1[NFLAG], d_flag2[NFLAG];
__device__ int   d_idx1[NFLAG],  d_idx2[NFLAG];
__device__ int   d_s2src[MAX_S2];
__device__ int   d_uniq2[MAX_U2];
__device__ int   d_uniq1[MAX_U1];
__device__ int   d_e1src[MAX_E1], d_e1dst[MAX_E1];
__device__ int   d_cnt[4];                 // 0:n_s2 1:n_u2 2:n_e1 3:n_u1
__device__ float d_h0[MAX_U1 * 64];
__device__ float d_as1[MAX_U1 * 2], d_ad1[MAX_U1 * 2];
__device__ float d_ht2[MAX_U2 * 128];
__device__ float d_as2[MAX_U2 * 2], d_ad2[MAX_U2 * 2];
__device__ volatile int d_bar_gen;
__device__ int   d_bar_cnt;

__device__ __forceinline__ float lrelu(float x, float s) {
    return x > 0.f ? x : s * x;
}

__device__ __forceinline__ void add_uniq2(int u) {
    if (atomicCAS(&d_flag2[u], 0, 1) == 0) {
        int p = atomicAdd(&d_cnt[1], 1);
        if (p < MAX_U2) { d_uniq2[p] = u; d_idx2[u] = p; }
    }
}
__device__ __forceinline__ void add_uniq1(int u) {
    if (atomicCAS(&d_flag1[u], 0, 1) == 0) {
        int p = atomicAdd(&d_cnt[3], 1);
        if (p < MAX_U1) { d_uniq1[p] = u; d_idx1[u] = p; }
    }
}

// grid-wide barrier: all NB blocks must call
__device__ __forceinline__ void gsync() {
    __syncthreads();
    if (threadIdx.x == 0) {
        __threadfence();
        int g = d_bar_gen;
        if (atomicAdd(&d_bar_cnt, 1) == NB - 1) {
            d_bar_cnt = 0;
            __threadfence();
            d_bar_gen = g + 1;
        } else {
            while (d_bar_gen == g) { __nanosleep(32); }
        }
        __threadfence();
    }
    __syncthreads();
}

__device__ __forceinline__ void p1_hit(const int* ei, int e) {
    int s = ei[e];
    int p = atomicAdd(&d_cnt[0], 1);
    if (p < MAX_S2) d_s2src[p] = s;
    add_uniq2(s); add_uniq1(s);
}
__device__ __forceinline__ void p2_hit(const int* ei, int e, int d) {
    int s = ei[e];
    int p = atomicAdd(&d_cnt[2], 1);
    if (p < MAX_E1) { d_e1src[p] = s; d_e1dst[p] = d; }
    add_uniq1(s);
}

__global__ void __launch_bounds__(NT, 1)
gat_fused(const float* __restrict__ x,   const int* __restrict__ ei,
          const float* __restrict__ W1,  const float* __restrict__ asrc1,
          const float* __restrict__ adst1, const float* __restrict__ b1,
          const float* __restrict__ g1,  const float* __restrict__ be1,
          const float* __restrict__ mn1, const float* __restrict__ vr1,
          const float* __restrict__ W2,  const float* __restrict__ asrc2,
          const float* __restrict__ adst2, const float* __restrict__ b2,
          const float* __restrict__ g2,  const float* __restrict__ be2,
          const float* __restrict__ mn2, const float* __restrict__ vr2,
          const float* __restrict__ fcW, const float* __restrict__ fcb,
          float* __restrict__ out, int E, int target)
{
    __shared__ unsigned s_bm[BMWORDS];             // 16 KB bitmap (P2)
    __shared__ int   s_si[MAXD + 8];
    __shared__ float s_a0[MAXD + 8], s_a1[MAXD + 8];
    __shared__ float xs[128], part[NT], red[NT], hs[128];
    __shared__ float ss[4], sd[4];
    __shared__ int   s_scnt;

    const int tid  = threadIdx.x;
    const int gtid = blockIdx.x * NT + tid;
    const int gstr = NB * NT;
    const int* dstp = ei + E;
    const int n4 = E >> 2;
    const int4* d4 = (const int4*)dstp;

    // ---------------- P1: edges into TARGET (4-way unrolled MLP) ------------
    if (gtid == 0) { add_uniq2(target); add_uniq1(target); }
    {
        for (int base = gtid; base < n4; base += gstr * SCAN_U) {
            int4 v[SCAN_U];
            int  idx[SCAN_U];
            #pragma unroll
            for (int u = 0; u < SCAN_U; u++) {
                idx[u] = base + u * gstr;
                if (idx[u] < n4) v[u] = d4[idx[u]];
                else v[u] = make_int4(-1, -1, -1, -1);
            }
            #pragma unroll
            for (int u = 0; u < SCAN_U; u++) {
                int i = idx[u];
                if (v[u].x == target) p1_hit(ei, 4*i+0);
                if (v[u].y == target) p1_hit(ei, 4*i+1);
                if (v[u].z == target) p1_hit(ei, 4*i+2);
                if (v[u].w == target) p1_hit(ei, 4*i+3);
            }
        }
        for (int e = (n4 << 2) + gtid; e < E; e += gstr)
            if (dstp[e] == target) p1_hit(ei, e);
    }
    gsync();

    // ---------------- P2: edges into uniq2 (shared bitmap, unrolled) --------
    {
        for (int w = tid; w < BMWORDS; w += NT) s_bm[w] = 0u;
        __syncthreads();
        int n2 = min(d_cnt[1], MAX_U2);
        for (int t = tid; t < n2; t += NT) {
            int u = d_uniq2[t];
            atomicOr(&s_bm[u >> 5], 1u << (u & 31));
        }
        __syncthreads();
        for (int base = gtid; base < n4; base += gstr * SCAN_U) {
            int4 v[SCAN_U];
            int  idx[SCAN_U];
            #pragma unroll
            for (int u = 0; u < SCAN_U; u++) {
                idx[u] = base + u * gstr;
                if (idx[u] < n4) v[u] = d4[idx[u]];
                else v[u] = make_int4(-1, -1, -1, -1);
            }
            #pragma unroll
            for (int u = 0; u < SCAN_U; u++) {
                int i = idx[u];
                int dx = v[u].x, dy = v[u].y, dz = v[u].z, dw = v[u].w;
                if (dx >= 0 && ((s_bm[dx >> 5] >> (dx & 31)) & 1u)) p2_hit(ei, 4*i+0, dx);
                if (dy >= 0 && ((s_bm[dy >> 5] >> (dy & 31)) & 1u)) p2_hit(ei, 4*i+1, dy);
                if (dz >= 0 && ((s_bm[dz >> 5] >> (dz & 31)) & 1u)) p2_hit(ei, 4*i+2, dz);
                if (dw >= 0 && ((s_bm[dw >> 5] >> (dw & 31)) & 1u)) p2_hit(ei, 4*i+3, dw);
            }
        }
        for (int e = (n4 << 2) + gtid; e < E; e += gstr) {
            int d = dstp[e];
            if ((s_bm[d >> 5] >> (d & 31)) & 1u) p2_hit(ei, e, d);
        }
    }
    gsync();

    // ---------------- P3: h0 = x@W1 for uniq1 nodes -------------------------
    {
        int nu = min(d_cnt[3], MAX_U1);
        int j  = tid & 63;
        int kq = tid >> 6;          // 0..7 -> 16 k's each
        for (int ui = blockIdx.x; ui < nu; ui += NB) {
            int u = d_uniq1[ui];
            if (tid < 128) xs[tid] = x[(size_t)u * 128 + tid];
            __syncthreads();
            float acc = 0.f;
            #pragma unroll
            for (int k = 0; k < 16; k++)
                acc = fmaf(xs[kq * 16 + k], W1[(kq * 16 + k) * 64 + j], acc);
            part[tid] = acc;
            __syncthreads();
            if (tid < 64) {
                float h = 0.f;
                #pragma unroll
                for (int q = 0; q < 8; q++) h += part[j + q * 64];
                d_h0[ui * 64 + j] = h;
                float vs = h * asrc1[j];
                float vd = h * adst1[j];
                #pragma unroll
                for (int o = 16; o > 0; o >>= 1) {
                    vs += __shfl_xor_sync(0xffffffffu, vs, o);
                    vd += __shfl_xor_sync(0xffffffffu, vd, o);
                }
                if ((j & 31) == 0) {
                    int hh = j >> 5;
                    d_as1[ui * 2 + hh] = vs;
                    d_ad1[ui * 2 + hh] = vd;
                }
            }
            __syncthreads();
        }
    }
    gsync();

    // ---------------- P4: layer-1 GAT + projection per uniq2 node -----------
    {
        int nv = min(d_cnt[1], MAX_U2);
        int ne = min(d_cnt[2], MAX_E1);
        for (int vi = blockIdx.x; vi < nv; vi += NB) {
            int vnode = d_uniq2[vi];
            int vIdx  = d_idx1[vnode];
            float ad0 = d_ad1[vIdx * 2 + 0];
            float ad1 = d_ad1[vIdx * 2 + 1];
            if (tid == 0) { s_scnt = 1; s_si[0] = vIdx; }   // self loop
            __syncthreads();
            for (int i = tid; i < ne; i += NT) {
                if (d_e1dst[i] == vnode) {
                    int p = atomicAdd(&s_scnt, 1);
                    if (p < MAXD) s_si[p] = d_idx1[d_e1src[i]];
                }
            }
            __syncthreads();
            int cnt = min(s_scnt, MAXD);
            float lm0 = -1e30f, lm1 = -1e30f;
            for (int k = tid; k < cnt; k += NT) {
                int si = s_si[k];
                float e0 = lrelu(d_as1[si * 2 + 0] + ad0, 0.2f);
                float e1 = lrelu(d_as1[si * 2 + 1] + ad1, 0.2f);
                s_a0[k] = e0; s_a1[k] = e1;
                lm0 = fmaxf(lm0, e0); lm1 = fmaxf(lm1, e1);
            }
            red[tid] = lm0; __syncthreads();
            for (int s = NT >> 1; s > 0; s >>= 1) { if (tid < s) red[tid] = fmaxf(red[tid], red[tid + s]); __syncthreads(); }
            float m0 = red[0]; __syncthreads();
            red[tid] = lm1; __syncthreads();
            for (int s = NT >> 1; s > 0; s >>= 1) { if (tid < s) red[tid] = fmaxf(red[tid], red[tid + s]); __syncthreads(); }
            float m1 = red[0]; __syncthreads();
            float ls0 = 0.f, ls1 = 0.f;
            for (int k = tid; k < cnt; k += NT) {
                float a0 = expf(s_a0[k] - m0);
                float a1 = expf(s_a1[k] - m1);
                s_a0[k] = a0; s_a1[k] = a1;
                ls0 += a0; ls1 += a1;
            }
            red[tid] = ls0; __syncthreads();
            for (int s = NT >> 1; s > 0; s >>= 1) { if (tid < s) red[tid] += red[tid + s]; __syncthreads(); }
            float sum0 = red[0]; __syncthreads();
            red[tid] = ls1; __syncthreads();
            for (int s = NT >> 1; s > 0; s >>= 1) { if (tid < s) red[tid] += red[tid + s]; __syncthreads(); }
            float sum1 = red[0]; __syncthreads();
            if (tid < 64) {
                int j = tid;
                const float* sa = (j >= 32) ? s_a1 : s_a0;
                float inv = (j >= 32) ? 1.f / (sum1 + 1e-16f) : 1.f / (sum0 + 1e-16f);
                float acc = 0.f;
                for (int k = 0; k < cnt; k++)
                    acc = fmaf(sa[k], d_h0[s_si[k] * 64 + j], acc);
                acc *= inv;
                float o = acc + b1[j];
                o = lrelu(o, 0.01f);
                o = (o - mn1[j]) * rsqrtf(vr1[j] + 1e-5f) * g1[j] + be1[j];
                hs[j] = o;
            }
            __syncthreads();
            if (tid < 128) {
                int j = tid;
                float acc = 0.f;
                #pragma unroll
                for (int k = 0; k < 64; k++) acc = fmaf(hs[k], W2[k * 128 + j], acc);
                d_ht2[vi * 128 + j] = acc;
                float vs = acc * asrc2[j];
                float vd = acc * adst2[j];
                #pragma unroll
                for (int o = 16; o > 0; o >>= 1) {
                    vs += __shfl_xor_sync(0xffffffffu, vs, o);
                    vd += __shfl_xor_sync(0xffffffffu, vd, o);
                }
                int w = j >> 5;
                if ((j & 31) == 0) { ss[w] = vs; sd[w] = vd; }
            }
            __syncthreads();
            if (tid == 0) {
                d_as2[vi * 2 + 0] = ss[0] + ss[1];
                d_as2[vi * 2 + 1] = ss[2] + ss[3];
                d_ad2[vi * 2 + 0] = sd[0] + sd[1];
                d_ad2[vi * 2 + 1] = sd[2] + sd[3];
            }
            __syncthreads();
        }
    }
    gsync();

    // ---------------- P5: layer-2 at TARGET + FC + cleanup (block 0) --------
    if (blockIdx.x != 0) return;
    {
        int u_t = d_idx2[target];
        float ad0 = d_ad2[u_t * 2 + 0];
        float ad1 = d_ad2[u_t * 2 + 1];
        int n = min(d_cnt[0], MAX_S2);
        int cnt = n + 1;                       // + self loop
        float lm0 = -1e30f, lm1 = -1e30f;
        for (int k = tid; k < cnt; k += NT) {
            int src = (k == n) ? target : d_s2src[k];
            int si = d_idx2[src];
            s_si[k] = si;
            float e0 = lrelu(d_as2[si * 2 + 0] + ad0, 0.2f);
            float e1 = lrelu(d_as2[si * 2 + 1] + ad1, 0.2f);
            s_a0[k] = e0; s_a1[k] = e1;
            lm0 = fmaxf(lm0, e0); lm1 = fmaxf(lm1, e1);
        }
        red[tid] = lm0; __syncthreads();
        for (int s = NT >> 1; s > 0; s >>= 1) { if (tid < s) red[tid] = fmaxf(red[tid], red[tid + s]); __syncthreads(); }
        float m0 = red[0]; __syncthreads();
        red[tid] = lm1; __syncthreads();
        for (int s = NT >> 1; s > 0; s >>= 1) { if (tid < s) red[tid] = fmaxf(red[tid], red[tid + s]); __syncthreads(); }
        float m1 = red[0]; __syncthreads();
        float ls0 = 0.f, ls1 = 0.f;
        for (int k = tid; k < cnt; k += NT) {
            float a0 = expf(s_a0[k] - m0);
            float a1 = expf(s_a1[k] - m1);
            s_a0[k] = a0; s_a1[k] = a1;
            ls0 += a0; ls1 += a1;
        }
        red[tid] = ls0; __syncthreads();
        for (int s = NT >> 1; s > 0; s >>= 1) { if (tid < s) red[tid] += red[tid + s]; __syncthreads(); }
        float sum0 = red[0]; __syncthreads();
        red[tid] = ls1; __syncthreads();
        for (int s = NT >> 1; s > 0; s >>= 1) { if (tid < s) red[tid] += red[tid + s]; __syncthreads(); }
        float sum1 = red[0]; __syncthreads();
        if (tid < 128) {
            int j = tid;
            const float* sa = (j >= 64) ? s_a1 : s_a0;
            float inv = (j >= 64) ? 1.f / (sum1 + 1e-16f) : 1.f / (sum0 + 1e-16f);
            float acc = 0.f;
            for (int k = 0; k < cnt; k++)
                acc = fmaf(sa[k], d_ht2[s_si[k] * 128 + j], acc);
            acc *= inv;
            float o = acc + b2[j];
            o = lrelu(o, 0.01f);
            o = (o - mn2[j]) * rsqrtf(vr2[j] + 1e-5f) * g2[j] + be2[j];
            hs[j] = o;
        }
        __syncthreads();
        if (tid < 60) {
            float r = fcb[tid];
            #pragma unroll 4
            for (int q = 0; q < 128; q++) r = fmaf(hs[q], fcW[q * 60 + tid], r);
            out[tid] = r;
        }
        // cleanup for next graph replay
        __syncthreads();
        int n1c = min(d_cnt[3], MAX_U1);
        for (int i = tid; i < n1c; i += NT) d_flag1[d_uniq1[i]] = 0;
        int n2c = min(d_cnt[1], MAX_U2);
        for (int i = tid; i < n2c; i += NT) d_flag2[d_uniq2[i]] = 0;
        __syncthreads();
        if (tid < 4) d_cnt[tid] = 0;
    }
}

// ---------------------------------------------------------------------------
extern "C" void kernel_launch(void* const* d_in, const int* in_sizes, int n_in,
                              void* d_out, int out_size) {
    const float* x      = (const float*)d_in[0];
    const int*   ei     = (const int*)d_in[1];     // int32 (JAX x64 disabled)
    const float* W1     = (const float*)d_in[2];
    const float* asrc1  = (const float*)d_in[3];
    const float* adst1  = (const float*)d_in[4];
    const float* b1     = (const float*)d_in[5];
    const float* g1     = (const float*)d_in[6];
    const float* be1    = (const float*)d_in[7];
    const float* mn1    = (const float*)d_in[8];
    const float* vr1    = (const float*)d_in[9];
    const float* W2     = (const float*)d_in[10];
    const float* asrc2  = (const float*)d_in[11];
    const float* adst2  = (const float*)d_in[12];
    const float* b2     = (const float*)d_in[13];
    const float* g2     = (const float*)d_in[14];
    const float* be2    = (const float*)d_in[15];
    const float* mn2    = (const float*)d_in[16];
    const float* vr2    = (const float*)d_in[17];
    const float* fcW    = (const float*)d_in[18];
    const float* fcb    = (const float*)d_in[19];
    float*       out    = (float*)d_out;

    int N = in_sizes[0] / 128;
    int E = in_sizes[1] / 2;
    int target = N - 1;

    gat_fused<<<NB, NT>>>(x, ei, W1, asrc1, adst1, b1, g1, be1, mn1, vr1,
                          W2, asrc2, adst2, b2, g2, be2, mn2, vr2, fcW, fcb,
                          out, E, target);
}